// round 16
// baseline (speedup 1.0000x reference)
#include <cuda_runtime.h>
#include <cstdint>

#define N 8192
#define NW 128          // max words per row (fallback sizing)
#define MAXR 1024       // register fixed-point handles cnt_a <= MAXR
#define MAXW 16         // and W <= MAXW
#define NB 128          // fused-kernel grid size (<= SM count: all resident)
typedef unsigned long long u64;
typedef unsigned int u32;

// ---------------- device globals (zero-initialized at module load) ----------------
__device__ u32 g_maxbox;
__device__ int g_cnt;      // valid boxes (score > 0.25)
__device__ int g_cnt_a;    // active valid boxes (positive area)
__device__ int g_barc;     // grid barrier arrive counter
__device__ u32 g_barg;     // grid barrier generation (monotonic across replays)
__device__ float g_x1[N], g_y1[N], g_x2[N], g_y2[N], g_sc[N];
__device__ u64 g_keys[N];  // (~mono(score))<<32 | idx<<1 | act
__device__ float g_sx1[N], g_sy1[N], g_sx2[N], g_sy2[N], g_ssc[N], g_sar[N];
__device__ int g_apos[N];  // sorted-active rank -> overall sorted position
__device__ u64 g_maskC[(size_t)NW * N];  // COLUMN-MAJOR mask: g_maskC[w*N + r]

__device__ __forceinline__ u32 fmono(float f) {
    u32 u = __float_as_uint(f);
    return (u & 0x80000000u) ? ~u : (u | 0x80000000u);
}

// software grid barrier: safe because all NB blocks are co-resident by construction
__device__ __forceinline__ void grid_sync() {
    __syncthreads();
    if (threadIdx.x == 0) {
        __threadfence();                         // publish this block's writes
        u32 gen = *(volatile u32*)&g_barg;
        if (atomicAdd(&g_barc, 1) == NB - 1) {
            g_barc = 0;
            __threadfence();
            atomicExch(&g_barg, gen + 1u);       // release
        } else {
            while (*(volatile u32*)&g_barg == gen) { }
        }
        __threadfence();                         // acquire
    }
    __syncthreads();
}

__global__ __launch_bounds__(256) void k_fused(const float* __restrict__ p,
                                               float* __restrict__ out) {
    __shared__ u64 sk[2048];                     // rank staging
    __shared__ float jx1[260], jy1[260], jx2[260], jy2[260], jar[260];  // mask tiles
    __shared__ u64 s_kept[2][MAXW];
    __shared__ int s_chg[2];
    __shared__ u64 s_keptF[NW];                  // fallback
    __shared__ unsigned char s_flag[NW * 64];    // fallback

    int tid = threadIdx.x, bid = blockIdx.x;
    int lane = tid & 31, warp = tid >> 5;

    // ================= phase 0: prep (decode + compact keys + zero out) ========
    if (bid < N / 256) {
        int i = bid * 256 + tid;                 // covers 0..N-1 exactly
        float cx = p[i], cy = p[N + i], pw = p[2*N + i], ph = p[3*N + i], s = p[4*N + i];
        float x1 = cx - pw*0.5f, y1 = cy - ph*0.5f, x2 = cx + pw*0.5f, y2 = cy + ph*0.5f;
        g_x1[i]=x1; g_y1[i]=y1; g_x2[i]=x2; g_y2[i]=y2; g_sc[i]=s;

        u32 m = fmono(fmaxf(fmaxf(x1,x2), fmaxf(y1,y2)));
        #pragma unroll
        for (int o = 16; o; o >>= 1) m = max(m, __shfl_xor_sync(0xffffffffu, m, o));
        if (lane == 0) atomicMax(&g_maxbox, m);

        bool valid = s > 0.25f;
        bool act = valid && (x2 > x1) && (y2 > y1);
        u32 vb = __ballot_sync(0xffffffffu, valid);
        u32 ab = __ballot_sync(0xffffffffu, act);
        if (vb) {
            int leader = __ffs(vb) - 1;
            int base = 0;
            if (lane == leader) {
                base = atomicAdd(&g_cnt, __popc(vb));
                if (ab) atomicAdd(&g_cnt_a, __popc(ab));
            }
            base = __shfl_sync(0xffffffffu, base, leader);
            if (valid) {
                int slot = base + __popc(vb & ((1u << lane) - 1u));
                g_keys[slot] = ((u64)(~fmono(s)) << 32) | ((u32)i << 1) | (act ? 1u : 0u);
            }
        }
    }
    for (int k = bid * 256 + tid; k < N * 6; k += NB * 256) out[k] = 0.0f;
    grid_sync();

    // ================= phase 1: O(n^2) rank sort =====================
    int cnt = *(volatile int*)&g_cnt;
    float fsc = ((*(volatile u32*)&g_maxbox) <= 0xBF800000u) ? 1.0f : (1.0f / 416.0f);

    for (int i0 = bid * 16; i0 < cnt; i0 += NB * 16) {
        int i = i0 + (tid >> 4);
        int part = tid & 15;
        u64 ki = (i < cnt) ? g_keys[i] : ~0ull;
        int rank_all = 0, rank_act = 0;
        for (int base = 0; base < cnt; base += 2048) {
            int lim = min(2048, cnt - base);
            __syncthreads();
            for (int t = tid; t < lim; t += 256) sk[t] = g_keys[base + t];
            __syncthreads();
            for (int j = part; j < lim; j += 16) {
                u64 kj = sk[j];
                int lt = kj < ki;
                rank_all += lt;
                rank_act += lt & (int)(kj & 1ull);
            }
        }
        #pragma unroll
        for (int o = 1; o < 16; o <<= 1) {
            rank_all += __shfl_xor_sync(0xffffffffu, rank_all, o);
            rank_act += __shfl_xor_sync(0xffffffffu, rank_act, o);
        }
        if (part == 0 && i < cnt) {
            int o = (int)((ki >> 1) & 0x1FFFull);
            bool act = (ki & 1ull) != 0ull;
            float x1 = g_x1[o], y1 = g_y1[o], x2 = g_x2[o], y2 = g_y2[o], s = g_sc[o];
            if (act) {
                int r = rank_act;
                g_sx1[r]=x1; g_sy1[r]=y1; g_sx2[r]=x2; g_sy2[r]=y2;
                g_ssc[r]=s;  g_sar[r]=(x2-x1)*(y2-y1);
                g_apos[r]=rank_all;
            } else {
                float* o6 = out + rank_all * 6;
                o6[0]=x1*fsc; o6[1]=y1*fsc; o6[2]=x2*fsc; o6[3]=y2*fsc; o6[4]=s; o6[5]=0.0f;
            }
        }
    }
    grid_sync();

    // ================= phase 2: IoU bitmask (lower triangle, column-major) =====
    int cnta = *(volatile int*)&g_cnt_a;
    if (cnta > 0) {
        int C = (cnta + 63) >> 6;
        int wtiles = (C + 3) >> 2;
        int ntiles = C * wtiles;
        for (int t = bid; t < ntiles; t += NB) {
            int c  = t / wtiles;
            int wt = t - c * wtiles;
            if (wt * 4 > c) continue;            // above diagonal: never read

            __syncthreads();
            {
                int j = wt * 256 + tid;
                int jm = (tid >> 6) * 65 + (tid & 63);
                bool ok = j < cnta;
                jx1[jm] = ok ? g_sx1[j] :  3.4e38f;
                jy1[jm] = ok ? g_sy1[j] :  3.4e38f;
                jx2[jm] = ok ? g_sx2[j] : -3.4e38f;
                jy2[jm] = ok ? g_sy2[j] : -3.4e38f;
                jar[jm] = ok ? g_sar[j] : 0.0f;
            }
            __syncthreads();

            int i = c * 64 + (tid & 63);
            int wl = tid >> 6;
            int w = wt * 4 + wl;
            if (i < cnta && w < C && w <= (i >> 6)) {
                float ix1 = g_sx1[i], iy1 = g_sy1[i], ix2 = g_sx2[i], iy2 = g_sy2[i], iar = g_sar[i];
                int base = wl * 65;
                u64 bits = 0;
                #pragma unroll 8
                for (int jj = 0; jj < 64; jj++) {
                    float bx1 = jx1[base + jj], by1 = jy1[base + jj];
                    float bx2 = jx2[base + jj], by2 = jy2[base + jj], ba = jar[base + jj];
                    float xx1 = fmaxf(ix1, bx1), yy1 = fmaxf(iy1, by1);
                    float xx2 = fminf(ix2, bx2), yy2 = fminf(iy2, by2);
                    float dx = fmaxf(xx2 - xx1, 0.0f), dy = fmaxf(yy2 - yy1, 0.0f);
                    float inter = dx * dy;
                    float uni = iar + ba - inter;
                    bool pred = (inter > 0.45f * uni) && (uni > 0.0f);
                    bits |= ((u64)pred) << jj;
                }
                g_maskC[(size_t)w * N + i] = bits;
            }
        }
    }
    grid_sync();

    // ================= phase 3: fixed-point greedy scan (block 0 only) =========
    if (bid != 0) return;
    cnt = cnta;
    int W = (cnt + 63) >> 6;

    if (cnt > 0 && cnt <= MAXR) {
        // thread owns 4 rows: tid, +256, +512, +768  (diag words <=4/8/12/16)
        int rA = tid, rB = tid + 256, rC = tid + 512, rD = tid + 768;
        int wA = rA >> 6, wB = rB >> 6, wC = rC >> 6, wD = rD >> 6;
        u64 rowA[4], rowB[8], rowC[12], rowD[16];
        #pragma unroll
        for (int w = 0; w < 4; w++) {
            u64 v = (rA < cnt && w <= wA) ? g_maskC[(size_t)w * N + rA] : 0ull;
            if (w == wA) v &= (1ull << (rA & 63)) - 1ull;
            rowA[w] = v;
        }
        #pragma unroll
        for (int w = 0; w < 8; w++) {
            u64 v = (rB < cnt && w <= wB) ? g_maskC[(size_t)w * N + rB] : 0ull;
            if (w == wB) v &= (1ull << (rB & 63)) - 1ull;
            rowB[w] = v;
        }
        #pragma unroll
        for (int w = 0; w < 12; w++) {
            u64 v = (rC < cnt && w <= wC) ? g_maskC[(size_t)w * N + rC] : 0ull;
            if (w == wC) v &= (1ull << (rC & 63)) - 1ull;
            rowC[w] = v;
        }
        #pragma unroll
        for (int w = 0; w < 16; w++) {
            u64 v = (rD < cnt && w <= wD) ? g_maskC[(size_t)w * N + rD] : 0ull;
            if (w == wD) v &= (1ull << (rD & 63)) - 1ull;
            rowD[w] = v;
        }
        auto candbits = [&](int base) -> u32 {
            if (cnt >= base + 32) return 0xffffffffu;
            if (cnt <= base) return 0u;
            return (1u << (cnt - base)) - 1u;
        };
        if (tid < 32) ((u32*)s_kept[0])[tid] = candbits(tid * 32);
        if (tid < 2) s_chg[tid] = 0;
        u32 oA = candbits(warp * 32),       oB = candbits(256 + warp * 32);
        u32 oC = candbits(512 + warp * 32), oD = candbits(768 + warp * 32);
        bool fA = false, fB = false, fC = false, fD = false;
        __syncthreads();

        int it = 0, pp = 0;
        for (;;) {
            const u64* kp = s_kept[pp];
            u64 aA = 0, aB = 0, aC = 0, aD = 0;
            #pragma unroll
            for (int w = 0; w < 4; w++)  { if (w > wA) break; aA |= rowA[w] & kp[w]; }
            #pragma unroll
            for (int w = 0; w < 8; w++)  { if (w > wB) break; aB |= rowB[w] & kp[w]; }
            #pragma unroll
            for (int w = 0; w < 12; w++) { if (w > wC) break; aC |= rowC[w] & kp[w]; }
            #pragma unroll
            for (int w = 0; w < 16; w++) { if (w > wD) break; aD |= rowD[w] & kp[w]; }
            fA = (rA < cnt) && (aA == 0ull);
            fB = (rB < cnt) && (aB == 0ull);
            fC = (rC < cnt) && (aC == 0ull);
            fD = (rD < cnt) && (aD == 0ull);
            u32 bA = __ballot_sync(0xffffffffu, fA);
            u32 bB = __ballot_sync(0xffffffffu, fB);
            u32 bC = __ballot_sync(0xffffffffu, fC);
            u32 bD = __ballot_sync(0xffffffffu, fD);
            if (lane == 0) {
                u32* kn = (u32*)s_kept[1 - pp];
                kn[warp] = bA; kn[8 + warp] = bB; kn[16 + warp] = bC; kn[24 + warp] = bD;
                if (bA != oA || bB != oB || bC != oC || bD != oD) s_chg[it & 1] = 1;
            }
            oA = bA; oB = bB; oC = bC; oD = bD;
            if (tid == 0) s_chg[(it + 1) & 1] = 0;
            __syncthreads();
            if (!s_chg[it & 1]) break;               // stable == greedy
            pp ^= 1;
            if (++it > MAXR) break;
        }

        int rr[4] = {rA, rB, rC, rD};
        bool ff[4] = {fA, fB, fC, fD};
        #pragma unroll
        for (int q = 0; q < 4; q++) {
            if (ff[q]) {
                int r = rr[q];
                float* o = out + g_apos[r] * 6;
                *(float2*)(o)     = make_float2(g_sx1[r] * fsc, g_sy1[r] * fsc);
                *(float2*)(o + 2) = make_float2(g_sx2[r] * fsc, g_sy2[r] * fsc);
                *(float2*)(o + 4) = make_float2(g_ssc[r], 0.0f);
            }
        }
    } else if (cnt > 0) {
        // generic fallback: dynamic fixed point from column-major mask
        for (int w = tid; w < W; w += 256) {
            int lim = cnt - w * 64;
            s_keptF[w] = (lim >= 64) ? ~0ull : ((1ull << lim) - 1ull);
        }
        for (int r = cnt + tid; r < W * 64; r += 256) s_flag[r] = 0;
        if (tid < 2) s_chg[tid] = 0;
        __syncthreads();
        int it = 0;
        for (;;) {
            for (int r = tid; r < cnt; r += 256) {
                int wj = r >> 6;
                u64 acc = g_maskC[(size_t)wj * N + r] & s_keptF[wj]
                          & ((1ull << (r & 63)) - 1ull);
                for (int w = 0; w < wj; w++)
                    acc |= g_maskC[(size_t)w * N + r] & s_keptF[w];
                s_flag[r] = (acc == 0ull);
            }
            __syncthreads();
            for (int w = warp; w < W; w += 8) {
                u32 lo = __ballot_sync(0xffffffffu, s_flag[w * 64 + lane] != 0);
                u32 hi = __ballot_sync(0xffffffffu, s_flag[w * 64 + 32 + lane] != 0);
                if (lane == 0) {
                    u64 nw_ = (u64)lo | ((u64)hi << 32);
                    if (nw_ != s_keptF[w]) { s_keptF[w] = nw_; s_chg[it & 1] = 1; }
                }
            }
            if (tid == 0) s_chg[(it + 1) & 1] = 0;
            __syncthreads();
            if (!s_chg[it & 1]) break;
            if (++it > N) break;
        }
        for (int r = tid; r < cnt; r += 256) {
            if ((s_keptF[r >> 6] >> (r & 63)) & 1ull) {
                float* o = out + g_apos[r] * 6;
                *(float2*)(o)     = make_float2(g_sx1[r] * fsc, g_sy1[r] * fsc);
                *(float2*)(o + 2) = make_float2(g_sx2[r] * fsc, g_sy2[r] * fsc);
                *(float2*)(o + 4) = make_float2(g_ssc[r], 0.0f);
            }
        }
    }

    // reset counters for the next graph replay
    if (tid == 0) { g_cnt = 0; g_cnt_a = 0; g_maxbox = 0u; }
}

extern "C" void kernel_launch(void* const* d_in, const int* in_sizes, int n_in,
                              void* d_out, int out_size) {
    const float* preds = (const float*)d_in[0];
    float* out = (float*)d_out;
    k_fused<<<NB, 256>>>(preds, out);
}